// round 2
// baseline (speedup 1.0000x reference)
#include <cuda_runtime.h>
#include <math.h>
#include <cstdint>

// ---------------- problem constants ----------------
constexpr int Bc = 2, Sc = 1024, Dc = 1024, Hc = 16, Lc = 9, Wc = 1024, Pc = 128, Vc = 256;
constexpr int DH = Dc / Hc;          // 64
constexpr int BS = Bc * Sc;          // 2048 rows

// ---------------- device scratch (allocation-free: static globals) ----------------
__device__ float g_x   [BS * Dc];            // residual stream
__device__ float g_h   [BS * Dc];            // LN output
__device__ float g_qkv [BS * 3 * Dc];        // self-attn qkv
__device__ float g_caq [BS * Dc];            // cross-attn q
__device__ float g_cakv[Bc * Pc * 2 * Dc];   // cross-attn k,v
__device__ float g_sc  [(long)Bc * Hc * Sc * Sc]; // attention scores (reused for CA)
__device__ float g_ao  [BS * Dc];            // attention output (pre-proj)
__device__ float g_ffn [BS * 4 * Dc];        // ffn hidden
__device__ int   g_pidx[BS];                 // cumsum of patch boundaries

// ---------------- reductions ----------------
__device__ __forceinline__ float block_sum(float v) {
    __shared__ float sh[32];
    int lane = threadIdx.x & 31, w = threadIdx.x >> 5;
    int nw = blockDim.x >> 5;
    #pragma unroll
    for (int o = 16; o; o >>= 1) v += __shfl_xor_sync(0xffffffffu, v, o);
    __syncthreads();
    if (lane == 0) sh[w] = v;
    __syncthreads();
    if (threadIdx.x == 0) {
        float t = 0.f;
        for (int i = 0; i < nw; i++) t += sh[i];
        sh[0] = t;
    }
    __syncthreads();
    return sh[0];
}

__device__ __forceinline__ float block_max(float v) {
    __shared__ float sh[32];
    int lane = threadIdx.x & 31, w = threadIdx.x >> 5;
    int nw = blockDim.x >> 5;
    #pragma unroll
    for (int o = 16; o; o >>= 1) v = fmaxf(v, __shfl_xor_sync(0xffffffffu, v, o));
    __syncthreads();
    if (lane == 0) sh[w] = v;
    __syncthreads();
    if (threadIdx.x == 0) {
        float t = -1e30f;
        for (int i = 0; i < nw; i++) t = fmaxf(t, sh[i]);
        sh[0] = t;
    }
    __syncthreads();
    return sh[0];
}

// ---------------- generic SGEMM ----------------
// C[m,n] = scale * sum_k A[m,k] * (BT ? B[n,k] : B[k,n])   (+bias[n]) (+gelu) (+res)
// Batched: per-z pointer offset = (z/nlo)*hi + (z%nlo)*lo  (covers (b,h) batching)
// EPI: 0 = none, 1 = +bias, 2 = +bias then GELU, 3 = +bias +residual
template<int EPI, bool BT, int BN_, int TN_>
__global__ __launch_bounds__(256, 2)
void gemm_k(const float* __restrict__ A, int lda, long sAhi, long sAlo, int nloA,
            const float* __restrict__ Bm, int ldb, long sBhi, long sBlo, int nloB,
            const float* __restrict__ bias,
            const float* __restrict__ Res,
            float* __restrict__ C, int ldc, long sChi, long sClo, int nloC,
            int K, float scale)
{
    constexpr int BM = 128, BK = 16, TM = 8;
    const int tid = threadIdx.x;
    const int z = blockIdx.z;
    A  += (long)(z / nloA) * sAhi + (long)(z % nloA) * sAlo;
    Bm += (long)(z / nloB) * sBhi + (long)(z % nloB) * sBlo;
    const long coff = (long)(z / nloC) * sChi + (long)(z % nloC) * sClo;
    C += coff;
    const float* res = (EPI == 3) ? Res + coff : nullptr;

    const int m0 = blockIdx.y * BM;
    const int n0 = blockIdx.x * BN_;

    __shared__ float As[BK][BM + 4];
    __shared__ float Bs[BK][BN_ + 4];

    float acc[TM][TN_];
    #pragma unroll
    for (int i = 0; i < TM; i++)
        #pragma unroll
        for (int j = 0; j < TN_; j++) acc[i][j] = 0.f;

    const int ty = tid >> 4;  // 0..15 -> M
    const int tx = tid & 15;  // 0..15 -> N

    for (int k0 = 0; k0 < K; k0 += BK) {
        // ---- load A tile [BM x BK], store transposed
        {
            int r = tid >> 1;
            int c = (tid & 1) * 8;
            const float* src = A + (long)(m0 + r) * lda + (k0 + c);
            float4 v0 = *(const float4*)src;
            float4 v1 = *(const float4*)(src + 4);
            As[c + 0][r] = v0.x; As[c + 1][r] = v0.y; As[c + 2][r] = v0.z; As[c + 3][r] = v0.w;
            As[c + 4][r] = v1.x; As[c + 5][r] = v1.y; As[c + 6][r] = v1.z; As[c + 7][r] = v1.w;
        }
        // ---- load B tile
        if constexpr (BT) {
            if constexpr (BN_ == 128) {
                int r = tid >> 1;
                int c = (tid & 1) * 8;
                const float* src = Bm + (long)(n0 + r) * ldb + (k0 + c);
                float4 v0 = *(const float4*)src;
                float4 v1 = *(const float4*)(src + 4);
                Bs[c + 0][r] = v0.x; Bs[c + 1][r] = v0.y; Bs[c + 2][r] = v0.z; Bs[c + 3][r] = v0.w;
                Bs[c + 4][r] = v1.x; Bs[c + 5][r] = v1.y; Bs[c + 6][r] = v1.z; Bs[c + 7][r] = v1.w;
            } else {
                int r = tid >> 2;
                int c = (tid & 3) * 4;
                float4 v = *(const float4*)(Bm + (long)(n0 + r) * ldb + (k0 + c));
                Bs[c + 0][r] = v.x; Bs[c + 1][r] = v.y; Bs[c + 2][r] = v.z; Bs[c + 3][r] = v.w;
            }
        } else {
            if constexpr (BN_ == 64) {
                int r = tid >> 4;          // k
                int c = (tid & 15) * 4;    // n
                float4 v = *(const float4*)(Bm + (long)(k0 + r) * ldb + (n0 + c));
                *(float4*)&Bs[r][c] = v;
            } else {
                int r = tid >> 4;
                int c = (tid & 15) * 8;
                const float* src = Bm + (long)(k0 + r) * ldb + (n0 + c);
                *(float4*)&Bs[r][c]     = *(const float4*)src;
                *(float4*)&Bs[r][c + 4] = *(const float4*)(src + 4);
            }
        }
        __syncthreads();

        #pragma unroll
        for (int k = 0; k < BK; k++) {
            float a[TM], b[TN_];
            *(float4*)&a[0] = *(const float4*)&As[k][ty * TM];
            *(float4*)&a[4] = *(const float4*)&As[k][ty * TM + 4];
            *(float4*)&b[0] = *(const float4*)&Bs[k][tx * TN_];
            if constexpr (TN_ == 8)
                *(float4*)&b[4] = *(const float4*)&Bs[k][tx * TN_ + 4];
            #pragma unroll
            for (int i = 0; i < TM; i++)
                #pragma unroll
                for (int j = 0; j < TN_; j++)
                    acc[i][j] = fmaf(a[i], b[j], acc[i][j]);
        }
        __syncthreads();
    }

    // ---- epilogue
    #pragma unroll
    for (int i = 0; i < TM; i++) {
        int m = m0 + ty * TM + i;
        float* crow = C + (long)m * ldc + n0 + tx * TN_;
        #pragma unroll
        for (int j4 = 0; j4 < TN_; j4 += 4) {
            float4 o;
            float* po = &o.x;
            #pragma unroll
            for (int j = 0; j < 4; j++) {
                float v = acc[i][j4 + j] * scale;
                if (EPI >= 1) v += bias[n0 + tx * TN_ + j4 + j];
                if (EPI == 2) v = 0.5f * v * (1.f + erff(v * 0.70710678118654752f));
                po[j] = v;
            }
            if (EPI == 3) {
                float4 rv = *(const float4*)(res + (long)m * ldc + n0 + tx * TN_ + j4);
                o.x += rv.x; o.y += rv.y; o.z += rv.z; o.w += rv.w;
            }
            *(float4*)(crow + j4) = o;
        }
    }
}

// ---------------- embedding ----------------
__global__ void embed_k(const int* __restrict__ seq, const float* __restrict__ bemb,
                        const float* __restrict__ pemb, float* __restrict__ x)
{
    int r = blockIdx.x;          // b*S + s
    int s = r % Sc;
    int tok = seq[r];
    int c = threadIdx.x * 4;
    float4 e = *(const float4*)(bemb + (long)tok * Dc + c);
    float4 p = *(const float4*)(pemb + (long)s * Dc + c);
    e.x += p.x; e.y += p.y; e.z += p.z; e.w += p.w;
    *(float4*)(x + (long)r * Dc + c) = e;
}

// ---------------- layernorm (row-per-block, D=1024, 256 threads) ----------------
__global__ void ln_k(const float* __restrict__ x, const float* __restrict__ g,
                     const float* __restrict__ b, float* __restrict__ out)
{
    const int row = blockIdx.x;
    const int tid = threadIdx.x;
    const float* xr = x + (long)row * Dc;
    float4 v = *(const float4*)(xr + tid * 4);
    float s = v.x + v.y + v.z + v.w;
    float tot = block_sum(s);
    float m = tot * (1.f / Dc);
    float dx0 = v.x - m, dx1 = v.y - m, dx2 = v.z - m, dx3 = v.w - m;
    float q = dx0 * dx0 + dx1 * dx1 + dx2 * dx2 + dx3 * dx3;
    float totq = block_sum(q);
    float rs = rsqrtf(totq * (1.f / Dc) + 1e-5f);
    float4 gg = *(const float4*)(g + tid * 4);
    float4 bb = *(const float4*)(b + tid * 4);
    float4 o;
    o.x = dx0 * rs * gg.x + bb.x;
    o.y = dx1 * rs * gg.y + bb.y;
    o.z = dx2 * rs * gg.z + bb.z;
    o.w = dx3 * rs * gg.w + bb.w;
    *(float4*)(out + (long)row * Dc + tid * 4) = o;
}

// ---------------- self-attn softmax (causal window) ----------------
__global__ void smax_sa(float* __restrict__ sc)
{
    const int i = blockIdx.x;     // query position
    const int z = blockIdx.y;     // b*H + h
    float* row = sc + ((long)z * Sc + i) * Sc;
    const int tid = threadIdx.x;  // 256
    int lo = i - Wc + 1; if (lo < 0) lo = 0;
    const int hi = i;
    float v[4];
    float mx = -1e30f;
    #pragma unroll
    for (int t = 0; t < 4; t++) {
        int j = tid + t * 256;
        bool ok = (j >= lo) && (j <= hi);
        v[t] = ok ? row[j] : -1e30f;
        mx = fmaxf(mx, v[t]);
    }
    mx = block_max(mx);
    float s = 0.f;
    #pragma unroll
    for (int t = 0; t < 4; t++) {
        int j = tid + t * 256;
        bool ok = (j >= lo) && (j <= hi);
        v[t] = ok ? expf(v[t] - mx) : 0.f;
        s += v[t];
    }
    s = block_sum(s);
    float inv = 1.f / s;
    #pragma unroll
    for (int t = 0; t < 4; t++)
        row[tid + t * 256] = v[t] * inv;
}

// ---------------- cross-attn softmax (patch mask) ----------------
__global__ void smax_ca(float* __restrict__ sc, const int* __restrict__ pidx)
{
    const int i = blockIdx.x;
    const int z = blockIdx.y;
    const int b = z / Hc;
    float* row = sc + ((long)z * Sc + i) * Pc;
    const int tid = threadIdx.x;  // 128
    const int lim = pidx[b * Sc + i];
    bool ok = tid <= lim;
    float v = ok ? row[tid] : -1e30f;
    float mx = block_max(v);
    float e = ok ? expf(v - mx) : 0.f;
    float s = block_sum(e);
    row[tid] = e / s;
}

// ---------------- inclusive cumsum of patch boundaries ----------------
__global__ void cumsum_k(const int* __restrict__ bd, int* __restrict__ pidx)
{
    __shared__ int s[Sc];
    const int b = blockIdx.x, t = threadIdx.x;  // 1024 threads
    s[t] = bd[b * Sc + t];
    __syncthreads();
    for (int off = 1; off < Sc; off <<= 1) {
        int v = (t >= off) ? s[t - off] : 0;
        __syncthreads();
        s[t] += v;
        __syncthreads();
    }
    pidx[b * Sc + t] = s[t];
}

// ---------------- launcher ----------------
extern "C" void kernel_launch(void* const* d_in, const int* in_sizes, int n_in,
                              void* d_out, int out_size)
{
    const int*   byte_seq  = (const int*)  d_in[0];
    const float* patch_rep = (const float*)d_in[1];
    const int*   patch_bd  = (const int*)  d_in[2];
    const float* byte_emb  = (const float*)d_in[3];
    const float* pos_emb   = (const float*)d_in[4];
    const float* sa_in_w   = (const float*)d_in[5];
    const float* sa_in_b   = (const float*)d_in[6];
    const float* sa_out_w  = (const float*)d_in[7];
    const float* sa_out_b  = (const float*)d_in[8];
    const float* ca_in_w   = (const float*)d_in[9];
    const float* ca_in_b   = (const float*)d_in[10];
    const float* ca_out_w  = (const float*)d_in[11];
    const float* ca_out_b  = (const float*)d_in[12];
    const float* ffn_w1    = (const float*)d_in[13];
    const float* ffn_b1    = (const float*)d_in[14];
    const float* ffn_w2    = (const float*)d_in[15];
    const float* ffn_b2    = (const float*)d_in[16];
    const float* ln_g      = (const float*)d_in[17];
    const float* ln_b      = (const float*)d_in[18];
    const float* norm_g    = (const float*)d_in[19];
    const float* norm_b    = (const float*)d_in[20];
    const float* out_w     = (const float*)d_in[21];
    float* out = (float*)d_out;

    float *gx, *gh, *gqkv, *gcaq, *gcakv, *gsc, *gao, *gffn;
    int* gpidx;
    cudaGetSymbolAddress((void**)&gx,    g_x);
    cudaGetSymbolAddress((void**)&gh,    g_h);
    cudaGetSymbolAddress((void**)&gqkv,  g_qkv);
    cudaGetSymbolAddress((void**)&gcaq,  g_caq);
    cudaGetSymbolAddress((void**)&gcakv, g_cakv);
    cudaGetSymbolAddress((void**)&gsc,   g_sc);
    cudaGetSymbolAddress((void**)&gao,   g_ao);
    cudaGetSymbolAddress((void**)&gffn,  g_ffn);
    cudaGetSymbolAddress((void**)&gpidx, g_pidx);

    // embedding + patch index cumsum
    embed_k<<<BS, 256>>>(byte_seq, byte_emb, pos_emb, gx);
    cumsum_k<<<Bc, Sc>>>(patch_bd, gpidx);

    for (int l = 0; l < Lc; l++) {
        // ===== self-attention =====
        ln_k<<<BS, 256>>>(gx, ln_g + (long)(l * 3 + 0) * Dc, ln_b + (long)(l * 3 + 0) * Dc, gh);

        // QKV: [BS, D] @ [3D, D]^T
        gemm_k<1, true, 128, 8><<<dim3(3 * Dc / 128, BS / 128, 1), 256>>>(
            gh, Dc, 0, 0, 1,
            sa_in_w + (long)l * 3 * Dc * Dc, Dc, 0, 0, 1,
            sa_in_b + (long)l * 3 * Dc, nullptr,
            gqkv, 3 * Dc, 0, 0, 1, Dc, 1.f);

        // scores[z=b*H+h]: Q @ K^T / 8
        gemm_k<0, true, 128, 8><<<dim3(Sc / 128, Sc / 128, Bc * Hc), 256>>>(
            gqkv,      3 * Dc, (long)Sc * 3 * Dc, DH, Hc,
            gqkv + Dc, 3 * Dc, (long)Sc * 3 * Dc, DH, Hc,
            nullptr, nullptr,
            gsc, Sc, (long)Sc * Sc, 0, 1,
            DH, 0.125f);

        smax_sa<<<dim3(Sc, Bc * Hc), 256>>>(gsc);

        // attn @ V
        gemm_k<0, false, 64, 4><<<dim3(1, Sc / 128, Bc * Hc), 256>>>(
            gsc, Sc, (long)Sc * Sc, 0, 1,
            gqkv + 2 * Dc, 3 * Dc, (long)Sc * 3 * Dc, DH, Hc,
            nullptr, nullptr,
            gao, Dc, (long)Sc * Dc, DH, Hc,
            Sc, 1.f);

        // out proj + residual
        gemm_k<3, true, 128, 8><<<dim3(Dc / 128, BS / 128, 1), 256>>>(
            gao, Dc, 0, 0, 1,
            sa_out_w + (long)l * Dc * Dc, Dc, 0, 0, 1,
            sa_out_b + (long)l * Dc, gx,
            gx, Dc, 0, 0, 1, Dc, 1.f);

        // ===== cross-attention =====
        ln_k<<<BS, 256>>>(gx, ln_g + (long)(l * 3 + 1) * Dc, ln_b + (long)(l * 3 + 1) * Dc, gh);

        // Q proj (rows 0:D of ca_in_w)
        gemm_k<1, true, 128, 8><<<dim3(Dc / 128, BS / 128, 1), 256>>>(
            gh, Dc, 0, 0, 1,
            ca_in_w + (long)l * 3 * Dc * Dc, Dc, 0, 0, 1,
            ca_in_b + (long)l * 3 * Dc, nullptr,
            gcaq, Dc, 0, 0, 1, Dc, 1.f);

        // KV proj on patch reps (rows D:3D of ca_in_w), M = B*P = 256
        gemm_k<1, true, 128, 8><<<dim3(2 * Dc / 128, (Bc * Pc) / 128, 1), 256>>>(
            patch_rep, Dc, 0, 0, 1,
            ca_in_w + (long)l * 3 * Dc * Dc + (long)Dc * Dc, Dc, 0, 0, 1,
            ca_in_b + (long)l * 3 * Dc + Dc, nullptr,
            gcakv, 2 * Dc, 0, 0, 1, Dc, 1.f);

        // CA scores: [S, P] per (b,h)
        gemm_k<0, true, 128, 8><<<dim3(Pc / 128, Sc / 128, Bc * Hc), 256>>>(
            gcaq,  Dc,     (long)Sc * Dc,     DH, Hc,
            gcakv, 2 * Dc, (long)Pc * 2 * Dc, DH, Hc,
            nullptr, nullptr,
            gsc, Pc, (long)Sc * Pc, 0, 1,
            DH, 0.125f);

        smax_ca<<<dim3(Sc, Bc * Hc), 128>>>(gsc, gpidx);

        // CA attn @ V (K = P = 128)
        gemm_k<0, false, 64, 4><<<dim3(1, Sc / 128, Bc * Hc), 256>>>(
            gsc, Pc, (long)Sc * Pc, 0, 1,
            gcakv + Dc, 2 * Dc, (long)Pc * 2 * Dc, DH, Hc,
            nullptr, nullptr,
            gao, Dc, (long)Sc * Dc, DH, Hc,
            Pc, 1.f);

        // CA out proj + residual
        gemm_k<3, true, 128, 8><<<dim3(Dc / 128, BS / 128, 1), 256>>>(
            gao, Dc, 0, 0, 1,
            ca_out_w + (long)l * Dc * Dc, Dc, 0, 0, 1,
            ca_out_b + (long)l * Dc, gx,
            gx, Dc, 0, 0, 1, Dc, 1.f);

        // ===== FFN =====
        ln_k<<<BS, 256>>>(gx, ln_g + (long)(l * 3 + 2) * Dc, ln_b + (long)(l * 3 + 2) * Dc, gh);

        // FFN1 + GELU
        gemm_k<2, true, 128, 8><<<dim3(4 * Dc / 128, BS / 128, 1), 256>>>(
            gh, Dc, 0, 0, 1,
            ffn_w1 + (long)l * 4 * Dc * Dc, Dc, 0, 0, 1,
            ffn_b1 + (long)l * 4 * Dc, nullptr,
            gffn, 4 * Dc, 0, 0, 1, Dc, 1.f);

        // FFN2 + residual
        gemm_k<3, true, 128, 8><<<dim3(Dc / 128, BS / 128, 1), 256>>>(
            gffn, 4 * Dc, 0, 0, 1,
            ffn_w2 + (long)l * Dc * 4 * Dc, 4 * Dc, 0, 0, 1,
            ffn_b2 + (long)l * Dc, gx,
            gx, Dc, 0, 0, 1, 4 * Dc, 1.f);
    }

    // final LN + vocab projection (no bias)
    ln_k<<<BS, 256>>>(gx, norm_g, norm_b, gh);
    gemm_k<0, true, 128, 8><<<dim3(Vc / 128, BS / 128, 1), 256>>>(
        gh, Dc, 0, 0, 1,
        out_w, Dc, 0, 0, 1,
        nullptr, nullptr,
        out, Vc, 0, 0, 1, Dc, 1.f);
}